// round 4
// baseline (speedup 1.0000x reference)
#include <cuda_runtime.h>
#include <cstdint>
#include <cstddef>

#define B_ 256
#define T_ 2048
#define I_ 128
#define H_ 64
#define G_ 256          // 4*H
#define M_ (B_*T_)      // 524288

// Scratch (device globals: allocation-free rule)
__device__ float g_pre[(size_t)M_ * G_];   // 512 MB
__device__ float g_h0 [(size_t)M_ * H_];   // 128 MB
__device__ float g_h1 [(size_t)M_ * H_];   // 128 MB

// ---------------------------------------------------------------- helpers
__device__ __forceinline__ float to_tf32(float x){
    unsigned u; asm("cvt.rna.tf32.f32 %0, %1;" : "=r"(u) : "f"(x));
    return __uint_as_float(u);
}

__device__ __forceinline__ void mma_tf32(float c[4], const unsigned a[4],
                                         unsigned b0, unsigned b1){
    asm volatile("mma.sync.aligned.m16n8k8.row.col.f32.tf32.tf32.f32 "
        "{%0,%1,%2,%3},{%4,%5,%6,%7},{%8,%9},{%0,%1,%2,%3};"
        : "+f"(c[0]),"+f"(c[1]),"+f"(c[2]),"+f"(c[3])
        : "r"(a[0]),"r"(a[1]),"r"(a[2]),"r"(a[3]),"r"(b0),"r"(b1));
}

__device__ __forceinline__ float sigmoid_f(float x){
    return __fdividef(1.f, 1.f + __expf(-x));
}
__device__ __forceinline__ float tanh_f(float x){
    return fmaf(-2.f, __fdividef(1.f, 1.f + __expf(2.f*x)), 1.f);
}

// ---------------------------------------------------------------- pre-GEMM
template<int K>
__global__ void __launch_bounds__(256,1)
gemm_pre(const float* __restrict__ A, const float* __restrict__ W,
         const float* __restrict__ b_ih, const float* __restrict__ b_hh,
         float* __restrict__ out)
{
    constexpr int BM = 128, N = G_, KP = K + 4;
    extern __shared__ float sm[];
    float* As = sm;                 // BM x KP
    float* Ws = sm + BM*KP;         // N x KP
    float* bs = Ws + N*KP;          // N

    const int tid = threadIdx.x;
    const size_t m0 = (size_t)blockIdx.x * BM;

    const float4* Ag = (const float4*)(A + m0*(size_t)K);
    for (int i = tid; i < BM*K/4; i += 256){
        float4 v = Ag[i];
        int fi = i*4, row = fi / K, col = fi % K;
        *(float4*)(As + row*KP + col) =
            make_float4(to_tf32(v.x), to_tf32(v.y), to_tf32(v.z), to_tf32(v.w));
    }
    const float4* Wg = (const float4*)W;
    for (int i = tid; i < N*K/4; i += 256){
        float4 v = Wg[i];
        int fi = i*4, row = fi / K, col = fi % K;
        *(float4*)(Ws + row*KP + col) =
            make_float4(to_tf32(v.x), to_tf32(v.y), to_tf32(v.z), to_tf32(v.w));
    }
    bs[tid] = b_ih[tid] + b_hh[tid];
    __syncthreads();

    const int warp = tid >> 5, lane = tid & 31;
    const int wm = warp >> 1, wn = warp & 1;
    const int gid = lane >> 2, tig = lane & 3;

    float c[2][16][4];
    #pragma unroll
    for (int a = 0; a < 2; a++)
        #pragma unroll
        for (int b = 0; b < 16; b++)
            #pragma unroll
            for (int d = 0; d < 4; d++) c[a][b][d] = 0.f;

    #pragma unroll
    for (int ks = 0; ks < K/8; ++ks){
        unsigned af[2][4];
        #pragma unroll
        for (int mt = 0; mt < 2; mt++){
            int r  = wm*32 + mt*16 + gid;
            int cc = ks*8 + tig;
            af[mt][0] = __float_as_uint(As[r*KP + cc]);
            af[mt][1] = __float_as_uint(As[(r+8)*KP + cc]);
            af[mt][2] = __float_as_uint(As[r*KP + cc + 4]);
            af[mt][3] = __float_as_uint(As[(r+8)*KP + cc + 4]);
        }
        #pragma unroll
        for (int nt = 0; nt < 16; nt++){
            int n  = wn*128 + nt*8 + gid;
            int kk = ks*8 + tig;
            unsigned b0 = __float_as_uint(Ws[n*KP + kk]);
            unsigned b1 = __float_as_uint(Ws[n*KP + kk + 4]);
            mma_tf32(c[0][nt], af[0], b0, b1);
            mma_tf32(c[1][nt], af[1], b0, b1);
        }
    }

    #pragma unroll
    for (int mt = 0; mt < 2; mt++){
        size_t r = m0 + wm*32 + mt*16 + gid;
        #pragma unroll
        for (int nt = 0; nt < 16; nt++){
            int col = wn*128 + nt*8 + 2*tig;
            float bb0 = bs[col], bb1 = bs[col+1];
            *(float2*)(out + r*N + col)
                = make_float2(c[mt][nt][0] + bb0, c[mt][nt][1] + bb1);
            *(float2*)(out + (r+8)*N + col)
                = make_float2(c[mt][nt][2] + bb0, c[mt][nt][3] + bb1);
        }
    }
}

// ---------------------------------------------------------------- LSTM scan
// Block = 2 sequences, 512 threads. Split-K: warp covers 16 gates; lanes 0-15
// hold K-half 0 (h[0..31]), lanes 16-31 K-half 1 (h[32..63]); 32 weights each
// packed {w,w} = 64 regs, no spill. Partials combined via shfl.bfly(16).
// pre is prefetched DISTANCE 4 through static-index register buffers so the
// LDG scoreboard wait lands 4 steps (>1100 cyc) after issue — no exposure.
__global__ void __launch_bounds__(512,1)
lstm_scan(const float* __restrict__ pre, const float* __restrict__ w_hh,
          float* __restrict__ h_out)
{
    __shared__ __align__(16) float2 h_s[H_];   // (row0,row1) pairs
    __shared__ float g_s[2][G_];               // [row][gate]

    const int tid  = threadIdx.x;
    const int warp = tid >> 5, lane = tid & 31;
    const int g    = warp * 16 + (lane & 15);  // gate 0..255
    const int k    = lane >> 4;                // K-half 0/1
    const int b0   = blockIdx.x * 2;
    const int gtype = g >> 6;                  // 2 => tanh

    if (tid < H_) h_s[tid] = make_float2(0.f, 0.f);

    // 32 weights for this (gate, k-half): wpk[j] = {w_hh[g][k*32+j]} x2
    unsigned long long wpk[32];
    {
        const float4* wr = (const float4*)(w_hh + g*H_ + k*32);
        #pragma unroll
        for (int k4 = 0; k4 < 8; k4++){
            float4 v = wr[k4];
            asm("mov.b64 %0,{%1,%1};" : "=l"(wpk[4*k4+0]) : "f"(v.x));
            asm("mov.b64 %0,{%1,%1};" : "=l"(wpk[4*k4+1]) : "f"(v.y));
            asm("mov.b64 %0,{%1,%1};" : "=l"(wpk[4*k4+2]) : "f"(v.z));
            asm("mov.b64 %0,{%1,%1};" : "=l"(wpk[4*k4+3]) : "f"(v.w));
        }
    }

    // pre pointers; K-half 0 lanes carry (row0,row1) pre into the accumulator
    const float* p0p = pre + ((size_t)b0     * T_) * G_ + g;
    const float* p1p = pre + ((size_t)(b0+1) * T_) * G_ + g;

    // distance-4 prefetch buffers (static indices only — stay in registers)
    float f0[4], f1[4];
    #pragma unroll
    for (int d = 0; d < 4; d++){ f0[d] = 0.f; f1[d] = 0.f; }
    if (k == 0){
        #pragma unroll
        for (int d = 0; d < 4; d++){
            f0[d] = __ldg(p0p + (size_t)d * G_);
            f1[d] = __ldg(p1p + (size_t)d * G_);
        }
    }

    // cell state register for updater threads (tid<128: row=tid>>6, j=tid&63)
    float creg = 0.f;
    const int urow = tid >> 6, uj = tid & 63;

    __syncthreads();

    for (int tb = 0; tb < T_; tb += 4){
        #pragma unroll
        for (int d = 0; d < 4; d++){
            const int t = tb + d;

            // consume value loaded 4 steps ago; immediately refill slot d
            float u0 = f0[d], u1 = f1[d];
            if (k == 0 && t + 4 < T_){
                f0[d] = __ldg(p0p + (size_t)(t + 4) * G_);
                f1[d] = __ldg(p1p + (size_t)(t + 4) * G_);
            }

            unsigned long long accA, accB, accC, accD;
            if (k == 0) asm("mov.b64 %0,{%1,%2};" : "=l"(accA) : "f"(u0), "f"(u1));
            else        asm("mov.b64 %0,{%1,%2};" : "=l"(accA) : "f"(0.f), "f"(0.f));
            asm("mov.b64 %0,{%1,%2};" : "=l"(accB) : "f"(0.f), "f"(0.f));
            asm("mov.b64 %0,{%1,%2};" : "=l"(accC) : "f"(0.f), "f"(0.f));
            asm("mov.b64 %0,{%1,%2};" : "=l"(accD) : "f"(0.f), "f"(0.f));

            // hv entry 2i -> h[k*32+4i, +4i+1]; entry 2i+1 -> h[k*32+4i+2, +4i+3]
            const ulonglong2* hv = ((const ulonglong2*)h_s) + k*16;
            #pragma unroll
            for (int i = 0; i < 8; i++){
                ulonglong2 hp0 = hv[2*i];
                ulonglong2 hp1 = hv[2*i+1];
                asm("fma.rn.f32x2 %0, %1, %2, %0;" : "+l"(accA) : "l"(wpk[4*i+0]), "l"(hp0.x));
                asm("fma.rn.f32x2 %0, %1, %2, %0;" : "+l"(accB) : "l"(wpk[4*i+1]), "l"(hp0.y));
                asm("fma.rn.f32x2 %0, %1, %2, %0;" : "+l"(accC) : "l"(wpk[4*i+2]), "l"(hp1.x));
                asm("fma.rn.f32x2 %0, %1, %2, %0;" : "+l"(accD) : "l"(wpk[4*i+3]), "l"(hp1.y));
            }

            unsigned long long accAB, accCD, acc;
            asm("add.rn.f32x2 %0, %1, %2;" : "=l"(accAB) : "l"(accA), "l"(accB));
            asm("add.rn.f32x2 %0, %1, %2;" : "=l"(accCD) : "l"(accC), "l"(accD));
            asm("add.rn.f32x2 %0, %1, %2;" : "=l"(acc)   : "l"(accAB), "l"(accCD));
            float a0, a1;
            asm("mov.b64 {%0,%1}, %2;" : "=f"(a0), "=f"(a1) : "l"(acc));

            // combine K-halves (butterfly gives full sum to both)
            a0 += __shfl_xor_sync(0xffffffffu, a0, 16);
            a1 += __shfl_xor_sync(0xffffffffu, a1, 16);

            // k-half 0 activates row 0, k-half 1 activates row 1
            float av = k ? a1 : a0;
            float v  = (gtype == 2) ? tanh_f(av) : sigmoid_f(av);
            g_s[k][g] = v;
            __syncthreads();

            if (tid < 128){
                float iv = g_s[urow][uj],       fv = g_s[urow][64+uj];
                float gv = g_s[urow][128+uj],   ov = g_s[urow][192+uj];
                creg = fmaf(fv, creg, iv*gv);
                float h = ov * tanh_f(creg);
                ((float*)&h_s[uj])[urow] = h;
                h_out[(((size_t)(b0+urow))*T_ + t)*H_ + uj] = h;
            }
            __syncthreads();
        }
    }
}

// ---------------------------------------------------------------- FC head
__global__ void fc_kernel(const float* __restrict__ h, const float* __restrict__ fw,
                          const float* __restrict__ fb, float* __restrict__ out)
{
    size_t m = (size_t)blockIdx.x * blockDim.x + threadIdx.x;
    const float4* hv = (const float4*)(h + m * H_);
    float acc = 0.f;
    #pragma unroll
    for (int i = 0; i < H_/4; i++){
        float4 a = hv[i];
        float4 w = __ldg(((const float4*)fw) + i);
        acc = fmaf(a.x, w.x, fmaf(a.y, w.y, fmaf(a.z, w.z, fmaf(a.w, w.w, acc))));
    }
    out[m] = acc + __ldg(fb);
}

// ---------------------------------------------------------------- launch
extern "C" void kernel_launch(void* const* d_in, const int* in_sizes, int n_in,
                              void* d_out, int out_size)
{
    const float* x     = (const float*)d_in[0];
    const float* w_ih0 = (const float*)d_in[1];
    const float* w_hh0 = (const float*)d_in[2];
    const float* b_ih0 = (const float*)d_in[3];
    const float* b_hh0 = (const float*)d_in[4];
    const float* w_ih1 = (const float*)d_in[5];
    const float* w_hh1 = (const float*)d_in[6];
    const float* b_ih1 = (const float*)d_in[7];
    const float* b_hh1 = (const float*)d_in[8];
    const float* w_ih2 = (const float*)d_in[9];
    const float* w_hh2 = (const float*)d_in[10];
    const float* b_ih2 = (const float*)d_in[11];
    const float* b_hh2 = (const float*)d_in[12];
    const float* fc_w  = (const float*)d_in[13];
    const float* fc_b  = (const float*)d_in[14];
    float* out = (float*)d_out;

    float *pre, *h0, *h1;
    cudaGetSymbolAddress((void**)&pre, g_pre);
    cudaGetSymbolAddress((void**)&h0,  g_h0);
    cudaGetSymbolAddress((void**)&h1,  g_h1);

    const int smem128 = (128+256)*(128+4)*4 + 256*4;
    const int smem64  = (128+256)*(64+4)*4  + 256*4;
    cudaFuncSetAttribute(gemm_pre<128>, cudaFuncAttributeMaxDynamicSharedMemorySize, smem128);
    cudaFuncSetAttribute(gemm_pre<64>,  cudaFuncAttributeMaxDynamicSharedMemorySize, smem64);

    gemm_pre<128><<<M_/128, 256, smem128>>>(x,  w_ih0, b_ih0, b_hh0, pre);
    lstm_scan    <<<B_/2,   512>>>(pre, w_hh0, h0);
    gemm_pre<64> <<<M_/128, 256, smem64 >>>(h0, w_ih1, b_ih1, b_hh1, pre);
    lstm_scan    <<<B_/2,   512>>>(pre, w_hh1, h1);
    gemm_pre<64> <<<M_/128, 256, smem64 >>>(h1, w_ih2, b_ih2, b_hh2, pre);
    lstm_scan    <<<B_/2,   512>>>(pre, w_hh2, h0);
    fc_kernel    <<<M_/256, 256>>>(h0, fc_w, fc_b, out);
}

// round 5
// speedup vs baseline: 1.5886x; 1.5886x over previous
#include <cuda_runtime.h>
#include <cstdint>
#include <cstddef>

#define B_ 256
#define T_ 2048
#define I_ 128
#define H_ 64
#define G_ 256          // 4*H
#define M_ (B_*T_)      // 524288

// Scratch (device globals: allocation-free rule)
__device__ float g_pre[(size_t)M_ * G_];   // 512 MB
__device__ float g_h0 [(size_t)M_ * H_];   // 128 MB
__device__ float g_h1 [(size_t)M_ * H_];   // 128 MB

// ---------------------------------------------------------------- helpers
__device__ __forceinline__ float to_tf32(float x){
    unsigned u; asm("cvt.rna.tf32.f32 %0, %1;" : "=r"(u) : "f"(x));
    return __uint_as_float(u);
}

__device__ __forceinline__ void mma_tf32(float c[4], const unsigned a[4],
                                         unsigned b0, unsigned b1){
    asm volatile("mma.sync.aligned.m16n8k8.row.col.f32.tf32.tf32.f32 "
        "{%0,%1,%2,%3},{%4,%5,%6,%7},{%8,%9},{%0,%1,%2,%3};"
        : "+f"(c[0]),"+f"(c[1]),"+f"(c[2]),"+f"(c[3])
        : "r"(a[0]),"r"(a[1]),"r"(a[2]),"r"(a[3]),"r"(b0),"r"(b1));
}

__device__ __forceinline__ float sigmoid_f(float x){
    return __fdividef(1.f, 1.f + __expf(-x));
}
__device__ __forceinline__ float tanh_f(float x){
    return fmaf(-2.f, __fdividef(1.f, 1.f + __expf(2.f*x)), 1.f);
}

// ---------------------------------------------------------------- pre-GEMM
template<int K>
__global__ void __launch_bounds__(256,1)
gemm_pre(const float* __restrict__ A, const float* __restrict__ W,
         const float* __restrict__ b_ih, const float* __restrict__ b_hh,
         float* __restrict__ out)
{
    constexpr int BM = 128, N = G_, KP = K + 4;
    extern __shared__ float sm[];
    float* As = sm;                 // BM x KP
    float* Ws = sm + BM*KP;         // N x KP
    float* bs = Ws + N*KP;          // N

    const int tid = threadIdx.x;
    const size_t m0 = (size_t)blockIdx.x * BM;

    const float4* Ag = (const float4*)(A + m0*(size_t)K);
    for (int i = tid; i < BM*K/4; i += 256){
        float4 v = Ag[i];
        int fi = i*4, row = fi / K, col = fi % K;
        *(float4*)(As + row*KP + col) =
            make_float4(to_tf32(v.x), to_tf32(v.y), to_tf32(v.z), to_tf32(v.w));
    }
    const float4* Wg = (const float4*)W;
    for (int i = tid; i < N*K/4; i += 256){
        float4 v = Wg[i];
        int fi = i*4, row = fi / K, col = fi % K;
        *(float4*)(Ws + row*KP + col) =
            make_float4(to_tf32(v.x), to_tf32(v.y), to_tf32(v.z), to_tf32(v.w));
    }
    bs[tid] = b_ih[tid] + b_hh[tid];
    __syncthreads();

    const int warp = tid >> 5, lane = tid & 31;
    const int wm = warp >> 1, wn = warp & 1;
    const int gid = lane >> 2, tig = lane & 3;

    float c[2][16][4];
    #pragma unroll
    for (int a = 0; a < 2; a++)
        #pragma unroll
        for (int b = 0; b < 16; b++)
            #pragma unroll
            for (int d = 0; d < 4; d++) c[a][b][d] = 0.f;

    #pragma unroll
    for (int ks = 0; ks < K/8; ++ks){
        unsigned af[2][4];
        #pragma unroll
        for (int mt = 0; mt < 2; mt++){
            int r  = wm*32 + mt*16 + gid;
            int cc = ks*8 + tig;
            af[mt][0] = __float_as_uint(As[r*KP + cc]);
            af[mt][1] = __float_as_uint(As[(r+8)*KP + cc]);
            af[mt][2] = __float_as_uint(As[r*KP + cc + 4]);
            af[mt][3] = __float_as_uint(As[(r+8)*KP + cc + 4]);
        }
        #pragma unroll
        for (int nt = 0; nt < 16; nt++){
            int n  = wn*128 + nt*8 + gid;
            int kk = ks*8 + tig;
            unsigned b0 = __float_as_uint(Ws[n*KP + kk]);
            unsigned b1 = __float_as_uint(Ws[n*KP + kk + 4]);
            mma_tf32(c[0][nt], af[0], b0, b1);
            mma_tf32(c[1][nt], af[1], b0, b1);
        }
    }

    #pragma unroll
    for (int mt = 0; mt < 2; mt++){
        size_t r = m0 + wm*32 + mt*16 + gid;
        #pragma unroll
        for (int nt = 0; nt < 16; nt++){
            int col = wn*128 + nt*8 + 2*tig;
            float bb0 = bs[col], bb1 = bs[col+1];
            *(float2*)(out + r*N + col)
                = make_float2(c[mt][nt][0] + bb0, c[mt][nt][1] + bb1);
            *(float2*)(out + (r+8)*N + col)
                = make_float2(c[mt][nt][2] + bb0, c[mt][nt][3] + bb1);
        }
    }
}

// ---------------------------------------------------------------- LSTM scan
// Block = 2 sequences, 256 threads (thread = gate). Weight packing is along
// K: wpk[i] = {w[g][2i], w[g][2i+1]} (natural float2 order, 32 u64 = 64 regs,
// NO spill, NO duplication). h is stored as natural pairs per row; one
// fma.rn.f32x2 accumulates even/odd K-partials for one row; both rows reuse
// the same weight registers. 4 independent chains of 16. Horizontal add at
// the end closes each dot product. Cell state in registers.
__global__ void __launch_bounds__(256,1)
lstm_scan(const float* __restrict__ pre, const float* __restrict__ w_hh,
          float* __restrict__ h_out)
{
    __shared__ __align__(16) float h2_s[2][H_];   // [row][j], row-contiguous
    __shared__ float g_s[2][G_];                  // [row][gate]

    const int tid = threadIdx.x;            // gate 0..255
    const int b0  = blockIdx.x * 2;
    const int gtype = tid >> 6;             // 2 => tanh

    if (tid < 2*H_) ((float*)h2_s)[tid] = 0.f;

    // 32 packed weight pairs: wpk[2k+0] = {w[4k],w[4k+1]}, wpk[2k+1] = {w[4k+2],w[4k+3]}
    unsigned long long wpk[32];
    {
        const float4* wr = (const float4*)(w_hh + tid*H_);
        #pragma unroll
        for (int k4 = 0; k4 < 16; k4++){
            float4 v = wr[k4];
            asm("mov.b64 %0,{%1,%2};" : "=l"(wpk[2*k4+0]) : "f"(v.x), "f"(v.y));
            asm("mov.b64 %0,{%1,%2};" : "=l"(wpk[2*k4+1]) : "f"(v.z), "f"(v.w));
        }
    }

    // pre pointers + distance-2 prefetch (unconditional, fully coalesced)
    const float* p0p = pre + ((size_t)b0     * T_) * G_ + tid;
    const float* p1p = pre + ((size_t)(b0+1) * T_) * G_ + tid;
    float p0 = p0p[0],  p1 = p1p[0];
    float q0 = p0p[G_], q1 = p1p[G_];

    // cell state register for updater threads (tid<128: row=tid>>6, j=tid&63)
    float creg = 0.f;
    const int urow = tid >> 6, uj = tid & 63;

    __syncthreads();

    for (int t = 0; t < T_; ++t){
        int tp = (t + 2 < T_) ? t + 2 : T_ - 1;
        float r0 = __ldg(p0p + (size_t)tp * G_);
        float r1 = __ldg(p1p + (size_t)tp * G_);

        // 4 chains: {row0 even-pair, row0 odd-pair, row1 even, row1 odd}
        unsigned long long aP0, aP1, aQ0, aQ1;
        asm("mov.b64 %0,{%1,%2};" : "=l"(aP0) : "f"(p0),  "f"(0.f));
        asm("mov.b64 %0,{%1,%2};" : "=l"(aQ0) : "f"(p1),  "f"(0.f));
        asm("mov.b64 %0,{%1,%2};" : "=l"(aP1) : "f"(0.f), "f"(0.f));
        asm("mov.b64 %0,{%1,%2};" : "=l"(aQ1) : "f"(0.f), "f"(0.f));

        const ulonglong2* h0v = (const ulonglong2*)h2_s[0];  // 16 x {h[4i..4i+3]}
        const ulonglong2* h1v = (const ulonglong2*)h2_s[1];
        #pragma unroll
        for (int i = 0; i < 16; i++){
            ulonglong2 x0 = h0v[i];
            ulonglong2 x1 = h1v[i];
            asm("fma.rn.f32x2 %0, %1, %2, %0;" : "+l"(aP0) : "l"(wpk[2*i+0]), "l"(x0.x));
            asm("fma.rn.f32x2 %0, %1, %2, %0;" : "+l"(aP1) : "l"(wpk[2*i+1]), "l"(x0.y));
            asm("fma.rn.f32x2 %0, %1, %2, %0;" : "+l"(aQ0) : "l"(wpk[2*i+0]), "l"(x1.x));
            asm("fma.rn.f32x2 %0, %1, %2, %0;" : "+l"(aQ1) : "l"(wpk[2*i+1]), "l"(x1.y));
        }

        unsigned long long aP, aQ;
        asm("add.rn.f32x2 %0, %1, %2;" : "=l"(aP) : "l"(aP0), "l"(aP1));
        asm("add.rn.f32x2 %0, %1, %2;" : "=l"(aQ) : "l"(aQ0), "l"(aQ1));
        float aPl, aPh, aQl, aQh;
        asm("mov.b64 {%0,%1}, %2;" : "=f"(aPl), "=f"(aPh) : "l"(aP));
        asm("mov.b64 {%0,%1}, %2;" : "=f"(aQl), "=f"(aQh) : "l"(aQ));
        float a0 = aPl + aPh;   // row0 gate pre-activation
        float a1 = aQl + aQh;   // row1

        float v0, v1;
        if (gtype == 2){ v0 = tanh_f(a0);    v1 = tanh_f(a1); }
        else           { v0 = sigmoid_f(a0); v1 = sigmoid_f(a1); }
        g_s[0][tid] = v0; g_s[1][tid] = v1;
        __syncthreads();

        if (tid < 128){
            float iv = g_s[urow][uj],       fv = g_s[urow][64+uj];
            float gv = g_s[urow][128+uj],   ov = g_s[urow][192+uj];
            creg = fmaf(fv, creg, iv*gv);
            float h = ov * tanh_f(creg);
            h2_s[urow][uj] = h;
            h_out[(((size_t)(b0+urow))*T_ + t)*H_ + uj] = h;
        }
        __syncthreads();
        p0 = q0; p1 = q1; q0 = r0; q1 = r1;
    }
}

// ---------------------------------------------------------------- FC head
__global__ void fc_kernel(const float* __restrict__ h, const float* __restrict__ fw,
                          const float* __restrict__ fb, float* __restrict__ out)
{
    size_t m = (size_t)blockIdx.x * blockDim.x + threadIdx.x;
    const float4* hv = (const float4*)(h + m * H_);
    float acc = 0.f;
    #pragma unroll
    for (int i = 0; i < H_/4; i++){
        float4 a = hv[i];
        float4 w = __ldg(((const float4*)fw) + i);
        acc = fmaf(a.x, w.x, fmaf(a.y, w.y, fmaf(a.z, w.z, fmaf(a.w, w.w, acc))));
    }
    out[m] = acc + __ldg(fb);
}

// ---------------------------------------------------------------- launch
extern "C" void kernel_launch(void* const* d_in, const int* in_sizes, int n_in,
                              void* d_out, int out_size)
{
    const float* x     = (const float*)d_in[0];
    const float* w_ih0 = (const float*)d_in[1];
    const float* w_hh0 = (const float*)d_in[2];
    const float* b_ih0 = (const float*)d_in[3];
    const float* b_hh0 = (const float*)d_in[4];
    const float* w_ih1 = (const float*)d_in[5];
    const float* w_hh1 = (const float*)d_in[6];
    const float* b_ih1 = (const float*)d_in[7];
    const float* b_hh1 = (const float*)d_in[8];
    const float* w_ih2 = (const float*)d_in[9];
    const float* w_hh2 = (const float*)d_in[10];
    const float* b_ih2 = (const float*)d_in[11];
    const float* b_hh2 = (const float*)d_in[12];
    const float* fc_w  = (const float*)d_in[13];
    const float* fc_b  = (const float*)d_in[14];
    float* out = (float*)d_out;

    float *pre, *h0, *h1;
    cudaGetSymbolAddress((void**)&pre, g_pre);
    cudaGetSymbolAddress((void**)&h0,  g_h0);
    cudaGetSymbolAddress((void**)&h1,  g_h1);

    const int smem128 = (128+256)*(128+4)*4 + 256*4;
    const int smem64  = (128+256)*(64+4)*4  + 256*4;
    cudaFuncSetAttribute(gemm_pre<128>, cudaFuncAttributeMaxDynamicSharedMemorySize, smem128);
    cudaFuncSetAttribute(gemm_pre<64>,  cudaFuncAttributeMaxDynamicSharedMemorySize, smem64);

    gemm_pre<128><<<M_/128, 256, smem128>>>(x,  w_ih0, b_ih0, b_hh0, pre);
    lstm_scan    <<<B_/2,   256>>>(pre, w_hh0, h0);
    gemm_pre<64> <<<M_/128, 256, smem64 >>>(h0, w_ih1, b_ih1, b_hh1, pre);
    lstm_scan    <<<B_/2,   256>>>(pre, w_hh1, h1);
    gemm_pre<64> <<<M_/128, 256, smem64 >>>(h1, w_ih2, b_ih2, b_hh2, pre);
    lstm_scan    <<<B_/2,   256>>>(pre, w_hh2, h0);
    fc_kernel    <<<M_/256, 256>>>(h0, fc_w, fc_b, out);
}

// round 6
// speedup vs baseline: 1.8713x; 1.1780x over previous
#include <cuda_runtime.h>
#include <cstdint>
#include <cstddef>

#define B_ 256
#define T_ 2048
#define I_ 128
#define H_ 64
#define G_ 256          // 4*H
#define M_ (B_*T_)      // 524288

// Scratch (device globals: allocation-free rule)
__device__ float g_pre[(size_t)M_ * G_];   // 512 MB
__device__ float g_h0 [(size_t)M_ * H_];   // 128 MB
__device__ float g_h1 [(size_t)M_ * H_];   // 128 MB

// ---------------------------------------------------------------- helpers
__device__ __forceinline__ float to_tf32(float x){
    unsigned u; asm("cvt.rna.tf32.f32 %0, %1;" : "=r"(u) : "f"(x));
    return __uint_as_float(u);
}

__device__ __forceinline__ void mma_tf32(float c[4], const unsigned a[4],
                                         unsigned b0, unsigned b1){
    asm volatile("mma.sync.aligned.m16n8k8.row.col.f32.tf32.tf32.f32 "
        "{%0,%1,%2,%3},{%4,%5,%6,%7},{%8,%9},{%0,%1,%2,%3};"
        : "+f"(c[0]),"+f"(c[1]),"+f"(c[2]),"+f"(c[3])
        : "r"(a[0]),"r"(a[1]),"r"(a[2]),"r"(a[3]),"r"(b0),"r"(b1));
}

__device__ __forceinline__ float sigmoid_f(float x){
    return __fdividef(1.f, 1.f + __expf(-x));
}

// ---------------------------------------------------------------- pre-GEMM
template<int K>
__global__ void __launch_bounds__(256,1)
gemm_pre(const float* __restrict__ A, const float* __restrict__ W,
         const float* __restrict__ b_ih, const float* __restrict__ b_hh,
         float* __restrict__ out)
{
    constexpr int BM = 128, N = G_, KP = K + 4;
    extern __shared__ float sm[];
    float* As = sm;                 // BM x KP
    float* Ws = sm + BM*KP;         // N x KP
    float* bs = Ws + N*KP;          // N

    const int tid = threadIdx.x;
    const size_t m0 = (size_t)blockIdx.x * BM;

    const float4* Ag = (const float4*)(A + m0*(size_t)K);
    for (int i = tid; i < BM*K/4; i += 256){
        float4 v = Ag[i];
        int fi = i*4, row = fi / K, col = fi % K;
        *(float4*)(As + row*KP + col) =
            make_float4(to_tf32(v.x), to_tf32(v.y), to_tf32(v.z), to_tf32(v.w));
    }
    const float4* Wg = (const float4*)W;
    for (int i = tid; i < N*K/4; i += 256){
        float4 v = Wg[i];
        int fi = i*4, row = fi / K, col = fi % K;
        *(float4*)(Ws + row*KP + col) =
            make_float4(to_tf32(v.x), to_tf32(v.y), to_tf32(v.z), to_tf32(v.w));
    }
    bs[tid] = b_ih[tid] + b_hh[tid];
    __syncthreads();

    const int warp = tid >> 5, lane = tid & 31;
    const int wm = warp >> 1, wn = warp & 1;
    const int gid = lane >> 2, tig = lane & 3;

    float c[2][16][4];
    #pragma unroll
    for (int a = 0; a < 2; a++)
        #pragma unroll
        for (int b = 0; b < 16; b++)
            #pragma unroll
            for (int d = 0; d < 4; d++) c[a][b][d] = 0.f;

    #pragma unroll
    for (int ks = 0; ks < K/8; ++ks){
        unsigned af[2][4];
        #pragma unroll
        for (int mt = 0; mt < 2; mt++){
            int r  = wm*32 + mt*16 + gid;
            int cc = ks*8 + tig;
            af[mt][0] = __float_as_uint(As[r*KP + cc]);
            af[mt][1] = __float_as_uint(As[(r+8)*KP + cc]);
            af[mt][2] = __float_as_uint(As[r*KP + cc + 4]);
            af[mt][3] = __float_as_uint(As[(r+8)*KP + cc + 4]);
        }
        #pragma unroll
        for (int nt = 0; nt < 16; nt++){
            int n  = wn*128 + nt*8 + gid;
            int kk = ks*8 + tig;
            unsigned b0 = __float_as_uint(Ws[n*KP + kk]);
            unsigned b1 = __float_as_uint(Ws[n*KP + kk + 4]);
            mma_tf32(c[0][nt], af[0], b0, b1);
            mma_tf32(c[1][nt], af[1], b0, b1);
        }
    }

    #pragma unroll
    for (int mt = 0; mt < 2; mt++){
        size_t r = m0 + wm*32 + mt*16 + gid;
        #pragma unroll
        for (int nt = 0; nt < 16; nt++){
            int col = wn*128 + nt*8 + 2*tig;
            float bb0 = bs[col], bb1 = bs[col+1];
            *(float2*)(out + r*N + col)
                = make_float2(c[mt][nt][0] + bb0, c[mt][nt][1] + bb1);
            *(float2*)(out + (r+8)*N + col)
                = make_float2(c[mt][nt][2] + bb0, c[mt][nt][3] + bb1);
        }
    }
}

// ---------------------------------------------------------------- LSTM scan
// Block = ONE sequence, 256 threads. tid -> (j = tid>>2, gt = tid&3): the 4
// gates of cell j live in 4 adjacent lanes of one warp, so the gate exchange
// is 3 shfls (no smem, no barrier) and the cell update is computed by all 4
// lanes redundantly. ONE __syncthreads per step (h_s double-buffered kills
// the WAR hazard). Weights K-paired in registers (32 u64, no spill).
// Activations branch-free: v = fma(sigmoid(a*m), m, b), (m,b)=(2,-1) tanh
// lanes, (1,0) sigmoid lanes. 2 blocks/SM for cross-block latency hiding.
__global__ void __launch_bounds__(256,2)
lstm_scan(const float* __restrict__ pre, const float* __restrict__ w_hh,
          float* __restrict__ h_out)
{
    __shared__ __align__(16) float h_s[2][H_];   // double buffer

    const int tid = threadIdx.x;
    const int j   = tid >> 2;          // cell 0..63
    const int gt  = tid & 3;           // 0=i 1=f 2=g 3=o
    const int grow = gt * H_ + j;      // row in w_hh / column in pre
    const int b   = blockIdx.x;

    // branch-free activation constants: gt==2 -> tanh via 2*sigmoid(2x)-1
    const float am = (gt == 2) ? 2.f : 1.f;
    const float ab = (gt == 2) ? -1.f : 0.f;

    if (tid < 2*H_) ((float*)h_s)[tid] = 0.f;

    // 32 packed weight pairs: wpk[m] = {w[2m], w[2m+1]}
    unsigned long long wpk[32];
    {
        const float4* wr = (const float4*)(w_hh + grow*H_);
        #pragma unroll
        for (int k4 = 0; k4 < 16; k4++){
            float4 v = wr[k4];
            asm("mov.b64 %0,{%1,%2};" : "=l"(wpk[2*k4+0]) : "f"(v.x), "f"(v.y));
            asm("mov.b64 %0,{%1,%2};" : "=l"(wpk[2*k4+1]) : "f"(v.z), "f"(v.w));
        }
    }

    // pre pointer + distance-2 prefetch ring (unconditional)
    const float* pp = pre + ((size_t)b * T_) * G_ + grow;
    float p0 = pp[0];
    float p1 = pp[G_];

    float creg = 0.f;                      // cell state (all 4 lanes of j)
    const unsigned lbase = (tid & 31) & ~3u;  // lane of gt==0 in this group

    __syncthreads();

    for (int t = 0; t < T_; ++t){
        int tp = (t + 2 < T_) ? t + 2 : T_ - 1;
        float pn = __ldg(pp + (size_t)tp * G_);

        const int rb = t & 1;
        // matvec: 32 FFMA2 in 4 chains of 8
        unsigned long long a0, a1, a2, a3;
        asm("mov.b64 %0,{%1,%2};" : "=l"(a0) : "f"(p0),  "f"(0.f));
        asm("mov.b64 %0,{%1,%2};" : "=l"(a1) : "f"(0.f), "f"(0.f));
        asm("mov.b64 %0,{%1,%2};" : "=l"(a2) : "f"(0.f), "f"(0.f));
        asm("mov.b64 %0,{%1,%2};" : "=l"(a3) : "f"(0.f), "f"(0.f));

        const ulonglong2* hv = (const ulonglong2*)h_s[rb];
        #pragma unroll
        for (int i = 0; i < 8; i++){
            ulonglong2 x = hv[i];
            ulonglong2 y = hv[i+8];
            asm("fma.rn.f32x2 %0, %1, %2, %0;" : "+l"(a0) : "l"(wpk[2*i+0]),  "l"(x.x));
            asm("fma.rn.f32x2 %0, %1, %2, %0;" : "+l"(a1) : "l"(wpk[2*i+1]),  "l"(x.y));
            asm("fma.rn.f32x2 %0, %1, %2, %0;" : "+l"(a2) : "l"(wpk[2*i+16]), "l"(y.x));
            asm("fma.rn.f32x2 %0, %1, %2, %0;" : "+l"(a3) : "l"(wpk[2*i+17]), "l"(y.y));
        }
        unsigned long long s01, s23, s;
        asm("add.rn.f32x2 %0, %1, %2;" : "=l"(s01) : "l"(a0), "l"(a1));
        asm("add.rn.f32x2 %0, %1, %2;" : "=l"(s23) : "l"(a2), "l"(a3));
        asm("add.rn.f32x2 %0, %1, %2;" : "=l"(s)   : "l"(s01), "l"(s23));
        float sl, sh;
        asm("mov.b64 {%0,%1}, %2;" : "=f"(sl), "=f"(sh) : "l"(s));
        float a = sl + sh;                         // gate pre-activation

        // branch-free activation
        float v = fmaf(sigmoid_f(a * am), am, ab);

        // gather the 4 gates of cell j from adjacent lanes
        float iv = __shfl_sync(0xffffffffu, v, lbase + 0, 32);
        float fv = __shfl_sync(0xffffffffu, v, lbase + 1, 32);
        float gv = __shfl_sync(0xffffffffu, v, lbase + 2, 32);
        float ov = __shfl_sync(0xffffffffu, v, lbase + 3, 32);

        // cell update (all 4 lanes compute identically)
        creg = fmaf(fv, creg, iv * gv);
        float th = fmaf(sigmoid_f(2.f * creg), 2.f, -1.f);   // tanh(c)
        float h  = ov * th;

        if (gt == 0){
            h_s[rb ^ 1][j] = h;
            h_out[((size_t)b * T_ + t) * H_ + j] = h;
        }
        p0 = p1; p1 = pn;
        __syncthreads();
    }
}

// ---------------------------------------------------------------- FC head
__global__ void fc_kernel(const float* __restrict__ h, const float* __restrict__ fw,
                          const float* __restrict__ fb, float* __restrict__ out)
{
    size_t m = (size_t)blockIdx.x * blockDim.x + threadIdx.x;
    const float4* hv = (const float4*)(h + m * H_);
    float acc = 0.f;
    #pragma unroll
    for (int i = 0; i < H_/4; i++){
        float4 a = hv[i];
        float4 w = __ldg(((const float4*)fw) + i);
        acc = fmaf(a.x, w.x, fmaf(a.y, w.y, fmaf(a.z, w.z, fmaf(a.w, w.w, acc))));
    }
    out[m] = acc + __ldg(fb);
}

// ---------------------------------------------------------------- launch
extern "C" void kernel_launch(void* const* d_in, const int* in_sizes, int n_in,
                              void* d_out, int out_size)
{
    const float* x     = (const float*)d_in[0];
    const float* w_ih0 = (const float*)d_in[1];
    const float* w_hh0 = (const float*)d_in[2];
    const float* b_ih0 = (const float*)d_in[3];
    const float* b_hh0 = (const float*)d_in[4];
    const float* w_ih1 = (const float*)d_in[5];
    const float* w_hh1 = (const float*)d_in[6];
    const float* b_ih1 = (const float*)d_in[7];
    const float* b_hh1 = (const float*)d_in[8];
    const float* w_ih2 = (const float*)d_in[9];
    const float* w_hh2 = (const float*)d_in[10];
    const float* b_ih2 = (const float*)d_in[11];
    const float* b_hh2 = (const float*)d_in[12];
    const float* fc_w  = (const float*)d_in[13];
    const float* fc_b  = (const float*)d_in[14];
    float* out = (float*)d_out;

    float *pre, *h0, *h1;
    cudaGetSymbolAddress((void**)&pre, g_pre);
    cudaGetSymbolAddress((void**)&h0,  g_h0);
    cudaGetSymbolAddress((void**)&h1,  g_h1);

    const int smem128 = (128+256)*(128+4)*4 + 256*4;
    const int smem64  = (128+256)*(64+4)*4  + 256*4;
    cudaFuncSetAttribute(gemm_pre<128>, cudaFuncAttributeMaxDynamicSharedMemorySize, smem128);
    cudaFuncSetAttribute(gemm_pre<64>,  cudaFuncAttributeMaxDynamicSharedMemorySize, smem64);

    gemm_pre<128><<<M_/128, 256, smem128>>>(x,  w_ih0, b_ih0, b_hh0, pre);
    lstm_scan    <<<B_,     256>>>(pre, w_hh0, h0);
    gemm_pre<64> <<<M_/128, 256, smem64 >>>(h0, w_ih1, b_ih1, b_hh1, pre);
    lstm_scan    <<<B_,     256>>>(pre, w_hh1, h1);
    gemm_pre<64> <<<M_/128, 256, smem64 >>>(h1, w_ih2, b_ih2, b_hh2, pre);
    lstm_scan    <<<B_,     256>>>(pre, w_hh2, h0);
    fc_kernel    <<<M_/256, 256>>>(h0, fc_w, fc_b, out);
}